// round 10
// baseline (speedup 1.0000x reference)
#include <cuda_runtime.h>

#define NN 50000
#define NE 800000
#define GRID 148
#define BLOCK 1024
#define GSTRIDE (GRID * BLOCK)
#define NWARPS (GRID * 32)
#define NTILE0 782      // ceil(50000/64) node tiles for gemm0
#define NSCAN 49        // ceil(50000/1024) scan tiles

// ---------------- scratch (device globals; no allocation) ----------------
__device__ int g_degi[NN];
__device__ int g_off[NN + 1];
__device__ int g_cursor[NN];
__device__ int g_bsum[64];
__device__ __align__(16) float2 g_edge[NE];     // (src_bits, weight), CSR by dst
__device__ __align__(16) float  g_lin0[NN * 64];// [n][64]: 0-31 self(Ws0), 32-63 neigh(Wn0)
__device__ __align__(16) float  g_lin1[NN * 32];// [n][32]: 0-15 self, 16-31 neigh
__device__ __align__(16) float2 g_lin2[NN];     // (self, neigh)
__device__ unsigned g_bar_cnt;
__device__ unsigned g_bar_gen;

__device__ __forceinline__ float tanh_fast(float x) {
    float e = __expf(2.0f * x);
    return 1.0f - __fdividef(2.0f, e + 1.0f);
}

// ---------------- software grid barrier (all 148 CTAs co-resident) ----------------
__device__ __forceinline__ void grid_sync() {
    __syncthreads();
    if (threadIdx.x == 0) {
        __threadfence();
        unsigned gen = *(volatile unsigned*)&g_bar_gen;
        unsigned t = atomicAdd(&g_bar_cnt, 1u);
        if (t == GRID - 1) {
            g_bar_cnt = 0;
            __threadfence();
            *(volatile unsigned*)&g_bar_gen = gen + 1u;
        } else {
            while (*(volatile unsigned*)&g_bar_gen == gen) { }
        }
        __threadfence();
    }
    __syncthreads();
}

__global__ __launch_bounds__(BLOCK, 1) void mega_kernel(
    const float* __restrict__ b_z,
    const int*   __restrict__ src,
    const int*   __restrict__ dst,
    const float* __restrict__ ew,
    const float* __restrict__ Ws0, const float* __restrict__ Wn0, const float* __restrict__ b0,
    const float* __restrict__ Ws1, const float* __restrict__ Wn1, const float* __restrict__ b1,
    const float* __restrict__ Ws2, const float* __restrict__ Wn2, const float* __restrict__ b2,
    float* __restrict__ outp)
{
    __shared__ float s_w[64 * 65];                 // P0: W0^T (pad 65); P4: W1
    __shared__ __align__(16) float s_h[4096];      // P0: h tile; P1: scan; P4: warp h rows
    __shared__ int   s_b[64];

    const int tid = threadIdx.x;
    const int bid = blockIdx.x;
    const int gtid = bid * BLOCK + tid;
    const int warp = tid >> 5;
    const int lane = tid & 31;

    // ================= P0: degree histogram + layer-0 GEMM =================
    for (int e = gtid; e < NE; e += GSTRIDE) atomicAdd(&g_degi[dst[e]], 1);

    for (int i = tid; i < 64 * 64; i += BLOCK) {
        int k = i >> 6, c = i & 63;
        s_w[c * 65 + k] = (c < 32) ? Ws0[k * 32 + c] : Wn0[k * 32 + (c - 32)];
    }

    {
        const int c = tid & 63;
        const int rg = tid >> 6;          // 0..15, 4 nodes each
        const int srow = tid >> 4;        // staging row
        const int skk = (tid & 15) << 2;  // staging col
        const float4 z4 = make_float4(0.f, 0.f, 0.f, 0.f);

        float4 reg = z4;
        if (bid < NTILE0) {
            int nd = bid * 64 + srow;
            reg = (nd < NN) ? *(const float4*)&b_z[(size_t)nd * 64 + skk] : z4;
        }
        for (int t = bid; t < NTILE0; t += GRID) {
            const int base = t * 64;
            __syncthreads();
            ((float4*)s_h)[tid] = reg;
            __syncthreads();
            // prefetch next tile while computing this one
            const int tn = t + GRID;
            if (tn < NTILE0) {
                int nd = tn * 64 + srow;
                reg = (nd < NN) ? *(const float4*)&b_z[(size_t)nd * 64 + skk] : z4;
            }
            const float* h0 = &s_h[(rg * 4 + 0) * 64];
            const float* h1 = &s_h[(rg * 4 + 1) * 64];
            const float* h2 = &s_h[(rg * 4 + 2) * 64];
            const float* h3 = &s_h[(rg * 4 + 3) * 64];
            float a0 = 0.f, a1 = 0.f, a2 = 0.f, a3 = 0.f;
#pragma unroll
            for (int k4 = 0; k4 < 16; k4++) {
                float4 ha = ((const float4*)h0)[k4];
                float4 hb = ((const float4*)h1)[k4];
                float4 hc = ((const float4*)h2)[k4];
                float4 hd = ((const float4*)h3)[k4];
                float w0 = s_w[c * 65 + k4 * 4 + 0];
                float w1 = s_w[c * 65 + k4 * 4 + 1];
                float w2 = s_w[c * 65 + k4 * 4 + 2];
                float w3 = s_w[c * 65 + k4 * 4 + 3];
                a0 = fmaf(ha.x, w0, a0); a0 = fmaf(ha.y, w1, a0); a0 = fmaf(ha.z, w2, a0); a0 = fmaf(ha.w, w3, a0);
                a1 = fmaf(hb.x, w0, a1); a1 = fmaf(hb.y, w1, a1); a1 = fmaf(hb.z, w2, a1); a1 = fmaf(hb.w, w3, a1);
                a2 = fmaf(hc.x, w0, a2); a2 = fmaf(hc.y, w1, a2); a2 = fmaf(hc.z, w2, a2); a2 = fmaf(hc.w, w3, a2);
                a3 = fmaf(hd.x, w0, a3); a3 = fmaf(hd.y, w1, a3); a3 = fmaf(hd.z, w2, a3); a3 = fmaf(hd.w, w3, a3);
            }
            const int nd0 = base + rg * 4;
            if (nd0 + 0 < NN) g_lin0[(size_t)(nd0 + 0) * 64 + c] = a0;
            if (nd0 + 1 < NN) g_lin0[(size_t)(nd0 + 1) * 64 + c] = a1;
            if (nd0 + 2 < NN) g_lin0[(size_t)(nd0 + 2) * 64 + c] = a2;
            if (nd0 + 3 < NN) g_lin0[(size_t)(nd0 + 3) * 64 + c] = a3;
        }
    }
    grid_sync();

    // ================= P1: per-tile scan of degrees =================
    if (bid < NSCAN) {
        int* ss = (int*)s_h;
        const int i = bid * BLOCK + tid;
        const int v = (i < NN) ? g_degi[i] : 0;
        ss[tid] = v;
        __syncthreads();
#pragma unroll
        for (int d = 1; d < BLOCK; d <<= 1) {
            int t2 = (tid >= d) ? ss[tid - d] : 0;
            __syncthreads();
            ss[tid] += t2;
            __syncthreads();
        }
        if (i < NN) g_off[i] = ss[tid] - v;
        if (tid == BLOCK - 1) g_bsum[bid] = ss[BLOCK - 1];
    }
    grid_sync();

    // ================= P2: apply tile offsets, init cursor =================
    if (bid < NSCAN) {
        if (tid < 64) s_b[tid] = (tid < NSCAN) ? g_bsum[tid] : 0;
        __syncthreads();
#pragma unroll
        for (int d = 1; d < 64; d <<= 1) {
            int t2 = (tid >= d && tid < 64) ? s_b[tid - d] : 0;
            __syncthreads();
            if (tid < 64) s_b[tid] += t2;
            __syncthreads();
        }
        const int add = (bid == 0) ? 0 : s_b[bid - 1];
        const int i = bid * BLOCK + tid;
        if (i < NN) {
            int o = g_off[i] + add;
            g_off[i] = o;
            g_cursor[i] = o;
        }
    }
    if (gtid == 0) g_off[NN] = NE;
    grid_sync();

    // ================= P3: CSR fill =================
    for (int e = gtid; e < NE; e += GSTRIDE) {
        int d = dst[e];
        int pos = atomicAdd(&g_cursor[d], 1);
        g_edge[pos] = make_float2(__int_as_float(src[e]), ew[e]);
    }
    grid_sync();

    // ================= P4: gather L0 + fused GEMM L1 =================
    for (int i = tid; i < 32 * 32; i += BLOCK) {
        int k = i >> 5, c = i & 31;
        s_w[i] = (c < 16) ? Ws1[k * 16 + c] : Wn1[k * 16 + (c - 16)];
    }
    __syncthreads();
    {
        float* s_hw = s_h;
        const int q = lane & 7, eslot = lane >> 3;   // CPG=8, ES=4
        float4 bv = make_float4(0.f, 0.f, 0.f, 0.f);
        if (lane < 8) bv = *(const float4*)&b0[4 * lane];

        for (int node = bid * 32 + warp; node < NN; node += NWARPS) {
            const int start = g_off[node];
            const int end = g_off[node + 1];
            float a0 = 0.f, a1 = 0.f, a2 = 0.f, a3 = 0.f;
            int k = start + eslot;
            if (k < end) {
                float2 ed = g_edge[k];
                while (true) {
                    const int kn = k + 4;
                    const bool more = (kn < end);
                    float2 edn;
                    if (more) edn = g_edge[kn];          // prefetch next edge
                    const int s = __float_as_int(ed.x);
                    const float w = ed.y;
                    float4 v = *(const float4*)&g_lin0[(size_t)s * 64 + 32 + 4 * q];
                    a0 = fmaf(w, v.x, a0); a1 = fmaf(w, v.y, a1);
                    a2 = fmaf(w, v.z, a2); a3 = fmaf(w, v.w, a3);
                    if (!more) break;
                    ed = edn; k = kn;
                }
            }
            a0 += __shfl_down_sync(0xffffffffu, a0, 16);
            a1 += __shfl_down_sync(0xffffffffu, a1, 16);
            a2 += __shfl_down_sync(0xffffffffu, a2, 16);
            a3 += __shfl_down_sync(0xffffffffu, a3, 16);
            a0 += __shfl_down_sync(0xffffffffu, a0, 8);
            a1 += __shfl_down_sync(0xffffffffu, a1, 8);
            a2 += __shfl_down_sync(0xffffffffu, a2, 8);
            a3 += __shfl_down_sync(0xffffffffu, a3, 8);
            if (lane < 8) {
                const float invdeg = 1.0f / fmaxf((float)(end - start), 1.0f);
                float4 sv = *(const float4*)&g_lin0[(size_t)node * 64 + 4 * lane];
                s_hw[warp * 32 + 4 * lane + 0] = tanh_fast(sv.x + a0 * invdeg + bv.x);
                s_hw[warp * 32 + 4 * lane + 1] = tanh_fast(sv.y + a1 * invdeg + bv.y);
                s_hw[warp * 32 + 4 * lane + 2] = tanh_fast(sv.z + a2 * invdeg + bv.z);
                s_hw[warp * 32 + 4 * lane + 3] = tanh_fast(sv.w + a3 * invdeg + bv.w);
            }
            __syncwarp();
            float acc = 0.f;
#pragma unroll 8
            for (int k2 = 0; k2 < 32; k2++)
                acc = fmaf(s_hw[warp * 32 + k2], s_w[k2 * 32 + lane], acc);
            g_lin1[(size_t)node * 32 + lane] = acc;
            __syncwarp();
        }
    }
    grid_sync();

    // ================= P5: gather L1 + fused GEMM L2 =================
    {
        const int q = lane & 3, eslot = lane >> 2;   // CPG=4, ES=8
        float4 bv1 = make_float4(0.f, 0.f, 0.f, 0.f);
        float4 wsv = bv1, wnv = bv1;
        if (lane < 4) {
            bv1 = *(const float4*)&b1[4 * lane];
            wsv = *(const float4*)&Ws2[4 * lane];
            wnv = *(const float4*)&Wn2[4 * lane];
        }
        for (int node = bid * 32 + warp; node < NN; node += NWARPS) {
            const int start = g_off[node];
            const int end = g_off[node + 1];
            float a0 = 0.f, a1 = 0.f, a2 = 0.f, a3 = 0.f;
            int k = start + eslot;
            if (k < end) {
                float2 ed = g_edge[k];
                while (true) {
                    const int kn = k + 8;
                    const bool more = (kn < end);
                    float2 edn;
                    if (more) edn = g_edge[kn];
                    const int s = __float_as_int(ed.x);
                    const float w = ed.y;
                    float4 v = *(const float4*)&g_lin1[(size_t)s * 32 + 16 + 4 * q];
                    a0 = fmaf(w, v.x, a0); a1 = fmaf(w, v.y, a1);
                    a2 = fmaf(w, v.z, a2); a3 = fmaf(w, v.w, a3);
                    if (!more) break;
                    ed = edn; k = kn;
                }
            }
#pragma unroll
            for (int off = 16; off >= 4; off >>= 1) {
                a0 += __shfl_down_sync(0xffffffffu, a0, off);
                a1 += __shfl_down_sync(0xffffffffu, a1, off);
                a2 += __shfl_down_sync(0xffffffffu, a2, off);
                a3 += __shfl_down_sync(0xffffffffu, a3, off);
            }
            float ps = 0.f, pn = 0.f;
            if (lane < 4) {
                const float invdeg = 1.0f / fmaxf((float)(end - start), 1.0f);
                float4 sv = *(const float4*)&g_lin1[(size_t)node * 32 + 4 * lane];
                float h0 = tanh_fast(sv.x + a0 * invdeg + bv1.x);
                float h1 = tanh_fast(sv.y + a1 * invdeg + bv1.y);
                float h2 = tanh_fast(sv.z + a2 * invdeg + bv1.z);
                float h3 = tanh_fast(sv.w + a3 * invdeg + bv1.w);
                ps = h0 * wsv.x + h1 * wsv.y + h2 * wsv.z + h3 * wsv.w;
                pn = h0 * wnv.x + h1 * wnv.y + h2 * wnv.z + h3 * wnv.w;
            }
            ps += __shfl_down_sync(0xffffffffu, ps, 2);
            pn += __shfl_down_sync(0xffffffffu, pn, 2);
            ps += __shfl_down_sync(0xffffffffu, ps, 1);
            pn += __shfl_down_sync(0xffffffffu, pn, 1);
            if (lane == 0) g_lin2[node] = make_float2(ps, pn);
        }
    }
    grid_sync();

    // ================= P6: gather L2 -> output =================
    {
        const float bias2 = __ldg(&b2[0]);
        for (int node = bid * 32 + warp; node < NN; node += NWARPS) {
            const int start = g_off[node];
            const int end = g_off[node + 1];
            float acc = 0.f;
            int k = start + lane;
            if (k < end) {
                float2 ed = g_edge[k];
                while (true) {
                    const int kn = k + 32;
                    const bool more = (kn < end);
                    float2 edn;
                    if (more) edn = g_edge[kn];
                    acc = fmaf(ed.y, g_lin2[__float_as_int(ed.x)].y, acc);
                    if (!more) break;
                    ed = edn; k = kn;
                }
            }
#pragma unroll
            for (int off = 16; off >= 1; off >>= 1)
                acc += __shfl_down_sync(0xffffffffu, acc, off);
            if (lane == 0) {
                const float invdeg = 1.0f / fmaxf((float)(end - start), 1.0f);
                outp[node] = g_lin2[node].x + acc * invdeg + bias2;
            }
        }
    }
}

// ---------------- launch ----------------
extern "C" void kernel_launch(void* const* d_in, const int* in_sizes, int n_in,
                              void* d_out, int out_size) {
    (void)in_sizes; (void)n_in; (void)out_size;
    const float* b_z = (const float*)d_in[0];
    const int*   src = (const int*)d_in[1];
    const int*   dst = (const int*)d_in[2];
    const float* ew  = (const float*)d_in[3];
    const float* Ws0 = (const float*)d_in[4];
    const float* Wn0 = (const float*)d_in[5];
    const float* b0  = (const float*)d_in[6];
    const float* Ws1 = (const float*)d_in[7];
    const float* Wn1 = (const float*)d_in[8];
    const float* b1  = (const float*)d_in[9];
    const float* Ws2 = (const float*)d_in[10];
    const float* Wn2 = (const float*)d_in[11];
    const float* b2  = (const float*)d_in[12];
    float* outp = (float*)d_out;

    int* p_degi;
    cudaGetSymbolAddress((void**)&p_degi, g_degi);
    cudaMemsetAsync(p_degi, 0, NN * sizeof(int), 0);

    mega_kernel<<<GRID, BLOCK>>>(b_z, src, dst, ew,
                                 Ws0, Wn0, b0, Ws1, Wn1, b1, Ws2, Wn2, b2, outp);
}

// round 13
// speedup vs baseline: 1.1191x; 1.1191x over previous
#include <cuda_runtime.h>

#define NN 50000
#define NE 800000
#define NSCAN 49     // ceil(50000/1024)

// ---------------- scratch (device globals; no allocation) ----------------
__device__ int g_degi[NN];
__device__ int g_off[NN + 1];
__device__ int g_cursor[NN];
__device__ int g_bsum[64];
__device__ __align__(16) float2 g_edge[NE];      // (src_bits, weight), CSR by dst
__device__ __align__(16) float  g_lin0[NN * 64]; // [n][64]: 0-31 self, 32-63 neigh
__device__ __align__(16) float  g_lin1[NN * 32]; // [n][32]: 0-15 self, 16-31 neigh
__device__ __align__(16) float2 g_lin2[NN];      // (self, neigh)

__device__ __forceinline__ float tanh_fast(float x) {
    float e = __expf(2.0f * x);
    return 1.0f - __fdividef(2.0f, e + 1.0f);
}

// ---------------- K1: degree histogram ----------------
__global__ void deg_kernel(const int* __restrict__ dst) {
    int e = blockIdx.x * blockDim.x + threadIdx.x;
    if (e < NE) atomicAdd(&g_degi[dst[e]], 1);
}

// ---------------- K2: per-tile exclusive scan (1024-wide, shfl-based) ----------------
__global__ void scanA() {
    __shared__ int wsum[32];
    const int tid = threadIdx.x;
    const int i = blockIdx.x * 1024 + tid;
    const int v = (i < NN) ? g_degi[i] : 0;
    int x = v;
#pragma unroll
    for (int d = 1; d < 32; d <<= 1) {
        int t = __shfl_up_sync(0xffffffffu, x, d);
        if ((tid & 31) >= d) x += t;
    }
    if ((tid & 31) == 31) wsum[tid >> 5] = x;
    __syncthreads();
    if (tid < 32) {
        int y = wsum[tid];
#pragma unroll
        for (int d = 1; d < 32; d <<= 1) {
            int t = __shfl_up_sync(0xffffffffu, y, d);
            if (tid >= d) y += t;
        }
        wsum[tid] = y;
    }
    __syncthreads();
    const int base = (tid >= 32) ? wsum[(tid >> 5) - 1] : 0;
    const int incl = base + x;
    if (i < NN) g_off[i] = incl - v;          // exclusive within tile
    if (tid == 1023) g_bsum[blockIdx.x] = incl;
}

// ---------------- K3: apply tile prefix + init cursor ----------------
__global__ void scanBC() {
    __shared__ int w2[2];
    const int tid = threadIdx.x;
    if (tid < 64) {
        int v = (tid < blockIdx.x && tid < NSCAN) ? g_bsum[tid] : 0;
#pragma unroll
        for (int d = 16; d >= 1; d >>= 1) v += __shfl_down_sync(0xffffffffu, v, d);
        if ((tid & 31) == 0) w2[tid >> 5] = v;
    }
    __syncthreads();
    const int add = w2[0] + w2[1];
    const int i = blockIdx.x * 1024 + tid;
    if (i < NN) {
        int o = g_off[i] + add;
        g_off[i] = o;
        g_cursor[i] = o;
    }
    if (blockIdx.x == 0 && tid == 0) g_off[NN] = NE;
}

// ---------------- K4: CSR fill ----------------
__global__ void fill_kernel(const int* __restrict__ src, const int* __restrict__ dst,
                            const float* __restrict__ ew) {
    int e = blockIdx.x * blockDim.x + threadIdx.x;
    if (e >= NE) return;
    int d = dst[e];
    int pos = atomicAdd(&g_cursor[d], 1);
    g_edge[pos] = make_float2(__int_as_float(src[e]), ew[e]);
}

// ---------------- K5: layer-0 GEMM: lin0[n][c] = b_z[n] . {Ws0|Wn0}[:,c] ----------------
__global__ void __launch_bounds__(256) gemm0_kernel(const float* __restrict__ h,
                                                    const float* __restrict__ Ws,
                                                    const float* __restrict__ Wn) {
    __shared__ __align__(16) float sh[4 * 64];
    const int tid = threadIdx.x;
    const int c = tid & 63;
    const int r = tid >> 6;
    float w[64];
    {
        const float* W = (c < 32) ? Ws : Wn;
        const int cc = (c < 32) ? c : (c - 32);
#pragma unroll
        for (int k = 0; k < 64; k++) w[k] = W[k * 32 + cc];
    }
    const int ntiles = (NN + 3) / 4;
    for (int tile = blockIdx.x; tile < ntiles; tile += gridDim.x) {
        const int base = tile * 4;
        __syncthreads();
        {   // stage 4x64 tile: 64 float4s
            if (tid < 64) {
                int nd = base + (tid >> 4);
                int kk = (tid & 15) << 2;
                float4 z = make_float4(0.f, 0.f, 0.f, 0.f);
                ((float4*)sh)[tid] = (nd < NN) ? *(const float4*)&h[(size_t)nd * 64 + kk] : z;
            }
        }
        __syncthreads();
        const int node = base + r;
        if (node < NN) {
            float acc = 0.0f;
#pragma unroll
            for (int k = 0; k < 64; k += 4) {
                float4 hv = *(const float4*)&sh[r * 64 + k];
                acc = fmaf(hv.x, w[k], acc); acc = fmaf(hv.y, w[k + 1], acc);
                acc = fmaf(hv.z, w[k + 2], acc); acc = fmaf(hv.w, w[k + 3], acc);
            }
            g_lin0[(size_t)node * 64 + c] = acc;
        }
    }
}

// ---------------- K6: gather L0 (unroll-4 MLP) + fused GEMM L1 ----------------
__global__ void __launch_bounds__(256) gather0_kernel(const float* __restrict__ Ws1,
                                                      const float* __restrict__ Wn1,
                                                      const float* __restrict__ b0) {
    __shared__ float s_w1[32 * 32];   // [k][c]
    for (int i = threadIdx.x; i < 32 * 32; i += 256) {
        int k = i >> 5, c = i & 31;
        s_w1[i] = (c < 16) ? Ws1[k * 16 + c] : Wn1[k * 16 + (c - 16)];
    }
    __syncthreads();

    const int node = blockIdx.x * 8 + (threadIdx.x >> 5);
    if (node >= NN) return;
    const int lane = threadIdx.x & 31;
    const int q = lane & 7, eslot = lane >> 3;   // 8 col-groups x 4 edge slots
    const int start = g_off[node];
    const int end = g_off[node + 1];

    float a0 = 0.f, a1 = 0.f, a2 = 0.f, a3 = 0.f;
    int k = start + eslot;
    // unrolled: 4 independent gathers in flight per lane
    for (; k + 12 < end; k += 16) {
        float2 e0 = g_edge[k];
        float2 e1 = g_edge[k + 4];
        float2 e2 = g_edge[k + 8];
        float2 e3 = g_edge[k + 12];
        float4 v0 = *(const float4*)&g_lin0[(size_t)__float_as_int(e0.x) * 64 + 32 + 4 * q];
        float4 v1 = *(const float4*)&g_lin0[(size_t)__float_as_int(e1.x) * 64 + 32 + 4 * q];
        float4 v2 = *(const float4*)&g_lin0[(size_t)__float_as_int(e2.x) * 64 + 32 + 4 * q];
        float4 v3 = *(const float4*)&g_lin0[(size_t)__float_as_int(e3.x) * 64 + 32 + 4 * q];
        a0 = fmaf(e0.y, v0.x, a0); a1 = fmaf(e0.y, v0.y, a1); a2 = fmaf(e0.y, v0.z, a2); a3 = fmaf(e0.y, v0.w, a3);
        a0 = fmaf(e1.y, v1.x, a0); a1 = fmaf(e1.y, v1.y, a1); a2 = fmaf(e1.y, v1.z, a2); a3 = fmaf(e1.y, v1.w, a3);
        a0 = fmaf(e2.y, v2.x, a0); a1 = fmaf(e2.y, v2.y, a1); a2 = fmaf(e2.y, v2.z, a2); a3 = fmaf(e2.y, v2.w, a3);
        a0 = fmaf(e3.y, v3.x, a0); a1 = fmaf(e3.y, v3.y, a1); a2 = fmaf(e3.y, v3.z, a2); a3 = fmaf(e3.y, v3.w, a3);
    }
    for (; k < end; k += 4) {
        float2 ed = g_edge[k];
        float4 v = *(const float4*)&g_lin0[(size_t)__float_as_int(ed.x) * 64 + 32 + 4 * q];
        a0 = fmaf(ed.y, v.x, a0); a1 = fmaf(ed.y, v.y, a1);
        a2 = fmaf(ed.y, v.z, a2); a3 = fmaf(ed.y, v.w, a3);
    }
    a0 += __shfl_down_sync(0xffffffffu, a0, 16);
    a1 += __shfl_down_sync(0xffffffffu, a1, 16);
    a2 += __shfl_down_sync(0xffffffffu, a2, 16);
    a3 += __shfl_down_sync(0xffffffffu, a3, 16);
    a0 += __shfl_down_sync(0xffffffffu, a0, 8);
    a1 += __shfl_down_sync(0xffffffffu, a1, 8);
    a2 += __shfl_down_sync(0xffffffffu, a2, 8);
    a3 += __shfl_down_sync(0xffffffffu, a3, 8);

    float4 h4 = make_float4(0.f, 0.f, 0.f, 0.f);
    if (lane < 8) {
        const float invdeg = 1.0f / fmaxf((float)(end - start), 1.0f);
        float4 sv = *(const float4*)&g_lin0[(size_t)node * 64 + 4 * lane];
        float4 bv = *(const float4*)&b0[4 * lane];
        h4.x = tanh_fast(sv.x + a0 * invdeg + bv.x);
        h4.y = tanh_fast(sv.y + a1 * invdeg + bv.y);
        h4.z = tanh_fast(sv.z + a2 * invdeg + bv.z);
        h4.w = tanh_fast(sv.w + a3 * invdeg + bv.w);
    }
    // fused GEMM L1: h[k] lives in component (k&3) of lane (k>>2)
    float acc = 0.f;
#pragma unroll
    for (int kk = 0; kk < 32; kk++) {
        float comp = ((kk & 3) == 0) ? h4.x : ((kk & 3) == 1) ? h4.y : ((kk & 3) == 2) ? h4.z : h4.w;
        float hk = __shfl_sync(0xffffffffu, comp, kk >> 2);
        acc = fmaf(hk, s_w1[kk * 32 + lane], acc);
    }
    g_lin1[(size_t)node * 32 + lane] = acc;
}

// ---------------- K7: gather L1 (unroll-2) + fused GEMM L2 ----------------
__global__ void __launch_bounds__(256) gather1_kernel(const float* __restrict__ b1,
                                                      const float* __restrict__ Ws2,
                                                      const float* __restrict__ Wn2) {
    const int node = blockIdx.x * 8 + (threadIdx.x >> 5);
    if (node >= NN) return;
    const int lane = threadIdx.x & 31;
    const int q = lane & 3, eslot = lane >> 2;   // 4 col-groups x 8 edge slots
    const int start = g_off[node];
    const int end = g_off[node + 1];

    float a0 = 0.f, a1 = 0.f, a2 = 0.f, a3 = 0.f;
    int k = start + eslot;
    for (; k + 8 < end; k += 16) {
        float2 e0 = g_edge[k];
        float2 e1 = g_edge[k + 8];
        float4 v0 = *(const float4*)&g_lin1[(size_t)__float_as_int(e0.x) * 32 + 16 + 4 * q];
        float4 v1 = *(const float4*)&g_lin1[(size_t)__float_as_int(e1.x) * 32 + 16 + 4 * q];
        a0 = fmaf(e0.y, v0.x, a0); a1 = fmaf(e0.y, v0.y, a1); a2 = fmaf(e0.y, v0.z, a2); a3 = fmaf(e0.y, v0.w, a3);
        a0 = fmaf(e1.y, v1.x, a0); a1 = fmaf(e1.y, v1.y, a1); a2 = fmaf(e1.y, v1.z, a2); a3 = fmaf(e1.y, v1.w, a3);
    }
    for (; k < end; k += 8) {
        float2 ed = g_edge[k];
        float4 v = *(const float4*)&g_lin1[(size_t)__float_as_int(ed.x) * 32 + 16 + 4 * q];
        a0 = fmaf(ed.y, v.x, a0); a1 = fmaf(ed.y, v.y, a1);
        a2 = fmaf(ed.y, v.z, a2); a3 = fmaf(ed.y, v.w, a3);
    }
#pragma unroll
    for (int off = 16; off >= 4; off >>= 1) {
        a0 += __shfl_down_sync(0xffffffffu, a0, off);
        a1 += __shfl_down_sync(0xffffffffu, a1, off);
        a2 += __shfl_down_sync(0xffffffffu, a2, off);
        a3 += __shfl_down_sync(0xffffffffu, a3, off);
    }
    float ps = 0.f, pn = 0.f;
    if (lane < 4) {
        const float invdeg = 1.0f / fmaxf((float)(end - start), 1.0f);
        float4 sv = *(const float4*)&g_lin1[(size_t)node * 32 + 4 * lane];
        float4 bv = *(const float4*)&b1[4 * lane];
        float4 wsv = *(const float4*)&Ws2[4 * lane];
        float4 wnv = *(const float4*)&Wn2[4 * lane];
        float h0 = tanh_fast(sv.x + a0 * invdeg + bv.x);
        float h1 = tanh_fast(sv.y + a1 * invdeg + bv.y);
        float h2 = tanh_fast(sv.z + a2 * invdeg + bv.z);
        float h3 = tanh_fast(sv.w + a3 * invdeg + bv.w);
        ps = h0 * wsv.x + h1 * wsv.y + h2 * wsv.z + h3 * wsv.w;
        pn = h0 * wnv.x + h1 * wnv.y + h2 * wnv.z + h3 * wnv.w;
    }
    ps += __shfl_down_sync(0xffffffffu, ps, 2);
    pn += __shfl_down_sync(0xffffffffu, pn, 2);
    ps += __shfl_down_sync(0xffffffffu, ps, 1);
    pn += __shfl_down_sync(0xffffffffu, pn, 1);
    if (lane == 0) g_lin2[node] = make_float2(ps, pn);
}

// ---------------- K8: gather L2 -> output ----------------
__global__ void __launch_bounds__(256) gather2_kernel(const float* __restrict__ b2,
                                                      float* __restrict__ outp) {
    const int node = blockIdx.x * 8 + (threadIdx.x >> 5);
    if (node >= NN) return;
    const int lane = threadIdx.x & 31;
    const int start = g_off[node];
    const int end = g_off[node + 1];
    float acc = 0.f;
    for (int k = start + lane; k < end; k += 32) {
        float2 ed = g_edge[k];
        acc = fmaf(ed.y, g_lin2[__float_as_int(ed.x)].y, acc);
    }
#pragma unroll
    for (int off = 16; off >= 1; off >>= 1)
        acc += __shfl_down_sync(0xffffffffu, acc, off);
    if (lane == 0) {
        const float invdeg = 1.0f / fmaxf((float)(end - start), 1.0f);
        outp[node] = g_lin2[node].x + acc * invdeg + __ldg(&b2[0]);
    }
}

// ---------------- launch ----------------
extern "C" void kernel_launch(void* const* d_in, const int* in_sizes, int n_in,
                              void* d_out, int out_size) {
    (void)in_sizes; (void)n_in; (void)out_size;
    const float* b_z = (const float*)d_in[0];
    const int*   src = (const int*)d_in[1];
    const int*   dst = (const int*)d_in[2];
    const float* ew  = (const float*)d_in[3];
    const float* Ws0 = (const float*)d_in[4];
    const float* Wn0 = (const float*)d_in[5];
    const float* b0  = (const float*)d_in[6];
    const float* Ws1 = (const float*)d_in[7];
    const float* Wn1 = (const float*)d_in[8];
    const float* b1  = (const float*)d_in[9];
    const float* Ws2 = (const float*)d_in[10];
    const float* Wn2 = (const float*)d_in[11];
    const float* b2  = (const float*)d_in[12];
    float* outp = (float*)d_out;

    int* p_degi;
    cudaGetSymbolAddress((void**)&p_degi, g_degi);
    cudaStream_t s = 0;

    cudaMemsetAsync(p_degi, 0, NN * sizeof(int), s);
    deg_kernel<<<(NE + 255) / 256, 256, 0, s>>>(dst);
    scanA<<<NSCAN, 1024, 0, s>>>();
    scanBC<<<NSCAN, 1024, 0, s>>>();
    fill_kernel<<<(NE + 255) / 256, 256, 0, s>>>(src, dst, ew);
    gemm0_kernel<<<592, 256, 0, s>>>(b_z, Ws0, Wn0);
    gather0_kernel<<<(NN + 7) / 8, 256, 0, s>>>(Ws1, Wn1, b0);
    gather1_kernel<<<(NN + 7) / 8, 256, 0, s>>>(b1, Ws2, Wn2);
    gather2_kernel<<<(NN + 7) / 8, 256, 0, s>>>(b2, outp);
}